// round 12
// baseline (speedup 1.0000x reference)
#include <cuda_runtime.h>
#include <cuda_fp16.h>
#include <math.h>
#include <stdint.h>

// ---------------- problem constants ----------------
#define D_    768
#define H_    12
#define DH_   64
#define F_    3072
#define L_    4
#define CH_   512
#define NSEQ  16              // B * (S/CH)
#define NTOK  (NSEQ * CH_)    // 8192
#define B_    8
#define S_    1024
#define W_    512
#define LNEPS 1e-12f
#define QKVN  (3 * D_)        // 2304

// weight layout offsets within per-layer block (transposed [N,K] fp16 hi/lo)
#define WOFF_Q  0
#define WOFF_O  (3*D_*D_)
#define WOFF_1  (4*D_*D_)            // [N=F, K=D]
#define WOFF_2  (4*D_*D_ + D_*F_)    // [N=D, K=F]
#define WSTRIDE (4*D_*D_ + 2*D_*F_)

// ---------------- scratch (device globals; no allocs allowed) ----------------
__device__ float g_h  [NTOK * D_];
__device__ float g_h1 [NTOK * D_];
__device__ float g_tmp[NTOK * D_];
__device__ float g_qkv[NTOK * QKVN];
__device__ float g_bqkv[L_ * QKVN];

__device__ __half g_hh  [NTOK * D_];   // activations: SINGLE fp16
__device__ __half g_h1h [NTOK * D_];
__device__ __half g_ctxh[NTOK * D_];
__device__ __half g_midh[NTOK * F_];
__device__ __half g_wthi[L_ * WSTRIDE];  // weights: fp16 hi + lo (exact to 2^-22)
__device__ __half g_wtlo[L_ * WSTRIDE];

// ---------------- helpers ----------------
__device__ __forceinline__ void split_fp16(float x, __half& hi, __half& lo) {
    hi = __float2half_rn(x);
    lo = __float2half_rn(x - __half2float(hi));
}

__device__ __forceinline__ float block_sum_256(float val, float* red) {
    int lane = threadIdx.x & 31, warp = threadIdx.x >> 5;
    #pragma unroll
    for (int o = 16; o > 0; o >>= 1) val += __shfl_xor_sync(0xffffffffu, val, o);
    if (lane == 0) red[warp] = val;
    __syncthreads();
    if (warp == 0) {
        float t = (lane < 8) ? red[lane] : 0.f;
        #pragma unroll
        for (int o = 4; o > 0; o >>= 1) t += __shfl_xor_sync(0xffffffffu, t, o);
        if (lane == 0) red[0] = t;
    }
    __syncthreads();
    float r = red[0];
    __syncthreads();
    return r;
}

// ---------------- batched weight transpose + fp16 split ----------------
#define WPREP_PER_LAYER 6912
__global__ void wprep_all(const float* __restrict__ Wq, const float* __restrict__ Wk,
                          const float* __restrict__ Wv, const float* __restrict__ Wo,
                          const float* __restrict__ W1, const float* __restrict__ W2,
                          __half* __restrict__ Thi,
                          __half* __restrict__ Tlo) {
    __shared__ float t[32][33];
    int id = blockIdx.x;
    int l = id / WPREP_PER_LAYER;
    int r = id % WPREP_PER_LAYER;

    const float* src;
    size_t doff = (size_t)l * WSTRIDE;
    int K, N, cols, local;
    if (r < 2304) {
        int mat = r / 576; local = r % 576;
        K = D_; N = D_; cols = 24;
        src = (mat == 0 ? Wq : mat == 1 ? Wk : mat == 2 ? Wv : Wo) + (size_t)l * D_ * D_;
        doff += (size_t)mat * D_ * D_;
    } else if (r < 4608) {
        local = r - 2304;
        K = D_; N = F_; cols = 96;
        src = W1 + (size_t)l * D_ * F_;
        doff += WOFF_1;
    } else {
        local = r - 4608;
        K = F_; N = D_; cols = 24;
        src = W2 + (size_t)l * F_ * D_;
        doff += WOFF_2;
    }
    int nb = (local % cols) * 32, kb = (local / cols) * 32;

    int tx = threadIdx.x, ty = threadIdx.y;
    #pragma unroll
    for (int i = 0; i < 4; i++)
        t[ty + 8 * i][tx] = src[(size_t)(kb + ty + 8 * i) * N + nb + tx];
    __syncthreads();
    #pragma unroll
    for (int i = 0; i < 4; i++) {
        float x = t[tx][ty + 8 * i];
        __half hi, lo;
        split_fp16(x, hi, lo);
        size_t o = doff + (size_t)(nb + ty + 8 * i) * K + kb + tx;
        Thi[o] = hi;
        Tlo[o] = lo;
    }
}

// pack [bq;bk;bv] per layer into contiguous 2304-vector
__global__ void biaspack_kernel(const float* __restrict__ bq,
                                const float* __restrict__ bk,
                                const float* __restrict__ bv,
                                float* __restrict__ dst) {
    int mat = blockIdx.x, l = blockIdx.y;
    const float* s = (mat == 0 ? bq : mat == 1 ? bk : bv) + l * D_;
    dst[(size_t)l * QKVN + mat * D_ + threadIdx.x] = s[threadIdx.x];
}

// ---------------- fused embedding + LayerNorm (+ fp16 out) ----------------
__global__ void embed_ln_kernel(const int* __restrict__ ids,
                                const float* __restrict__ we,
                                const float* __restrict__ pe,
                                const float* __restrict__ te,
                                const float* __restrict__ g,
                                const float* __restrict__ b,
                                float* __restrict__ out,
                                __half* __restrict__ oh) {
    __shared__ float red[32];
    int row = blockIdx.x;
    int pos = row % CH_;
    int id  = ids[row];
    float v[3];
    float s = 0.f;
    #pragma unroll
    for (int i = 0; i < 3; i++) {
        int d = i * 256 + threadIdx.x;
        v[i] = we[(size_t)id * D_ + d] + pe[pos * D_ + d] + te[d];
        s += v[i];
    }
    float mu = block_sum_256(s, red) * (1.f / D_);
    float sq = 0.f;
    #pragma unroll
    for (int i = 0; i < 3; i++) { float t = v[i] - mu; sq += t * t; }
    float rstd = rsqrtf(block_sum_256(sq, red) * (1.f / D_) + LNEPS);
    #pragma unroll
    for (int i = 0; i < 3; i++) {
        int d = i * 256 + threadIdx.x;
        float y = (v[i] - mu) * rstd * g[d] + b[d];
        size_t idx = (size_t)row * D_ + d;
        out[idx] = y;
        oh[idx] = __float2half_rn(y);
    }
}

// ---------------- residual + LayerNorm (+ fp16 out) ----------------
__global__ void ln_res_kernel(const float* __restrict__ X,
                              const float* __restrict__ Y,
                              const float* __restrict__ g,
                              const float* __restrict__ b,
                              float* __restrict__ out,
                              __half* __restrict__ oh) {
    __shared__ float red[32];
    int row = blockIdx.x;
    float v[3];
    float s = 0.f;
    #pragma unroll
    for (int i = 0; i < 3; i++) {
        int d = i * 256 + threadIdx.x;
        size_t idx = (size_t)row * D_ + d;
        v[i] = X[idx] + Y[idx];
        s += v[i];
    }
    float mu = block_sum_256(s, red) * (1.f / D_);
    float sq = 0.f;
    #pragma unroll
    for (int i = 0; i < 3; i++) { float t = v[i] - mu; sq += t * t; }
    float rstd = rsqrtf(block_sum_256(sq, red) * (1.f / D_) + LNEPS);
    #pragma unroll
    for (int i = 0; i < 3; i++) {
        int d = i * 256 + threadIdx.x;
        float y = (v[i] - mu) * rstd * g[d] + b[d];
        size_t idx = (size_t)row * D_ + d;
        out[idx] = y;
        oh[idx] = __float2half_rn(y);
    }
}

// ============================================================================
// fp16x2 tensor-core GEMM via mma.sync.m16n8k16.f32.f16.f16.f32:
// C[M,N] = A_fp16[M,K] @ (Bh + Bl)^T (B stored [N,K]) + bias.
// Activation A rounded to fp16 (err 2^-11, incoherent over K); weights split
// hi+lo (exact). 2 MMA terms instead of 3 (bf16x3) -> 2/3 the tensor work.
// CTA tile 128x128, K-chunk 64, 4-stage cp.async pipeline (48KB/stage=192KB).
// 512 threads = 16 warps (4m x 4n), warp tile 32x32.
// ============================================================================
#define GSTAGES 4
#define STAGE_BYTES 49152u               // A 16KB + Bh 16KB + Bl 16KB
#define GEMM_SMEM (GSTAGES * 49152)      // 192KB

__device__ __forceinline__ void ldsm4(uint32_t* r, uint32_t addr) {
    asm volatile("ldmatrix.sync.aligned.m8n8.x4.shared.b16 {%0,%1,%2,%3}, [%4];"
                 : "=r"(r[0]), "=r"(r[1]), "=r"(r[2]), "=r"(r[3]) : "r"(addr));
}

__device__ __forceinline__ void mma16816h(float* d, const uint32_t* a, const uint32_t* b) {
    asm volatile(
        "mma.sync.aligned.m16n8k16.row.col.f32.f16.f16.f32 "
        "{%0,%1,%2,%3}, {%4,%5,%6,%7}, {%8,%9}, {%0,%1,%2,%3};"
        : "+f"(d[0]), "+f"(d[1]), "+f"(d[2]), "+f"(d[3])
        : "r"(a[0]), "r"(a[1]), "r"(a[2]), "r"(a[3]), "r"(b[0]), "r"(b[1]));
}

__device__ __forceinline__ uint32_t sw128(uint32_t off) {
    return off ^ ((off >> 3) & 0x70);
}

__device__ __forceinline__ void cp_row128(uint32_t sdst_base, const __half* src, int row) {
    #pragma unroll
    for (int i = 0; i < 8; i++) {
        uint32_t off = (uint32_t)row * 128u + (uint32_t)i * 16u;
        uint32_t d = sdst_base + sw128(off);
        asm volatile("cp.async.cg.shared.global [%0], [%1], 16;"
                     :: "r"(d), "l"(src + i * 8) : "memory");
    }
}

template <bool GELU_H>
__global__ void __launch_bounds__(512)
gemm_tc(const __half* __restrict__ A,
        const __half* __restrict__ Bhi, const __half* __restrict__ Blo,
        const float* __restrict__ bias,
        float* __restrict__ Cf,
        __half* __restrict__ Ch,
        int M, int N, int K) {
    extern __shared__ char smem[];
    const int tid = threadIdx.x;
    const int wid = tid >> 5, lane = tid & 31;
    const int m0 = blockIdx.y * 128, n0 = blockIdx.x * 128;
    const int wm0 = (wid & 3) * 32;
    const int wn0 = (wid >> 2) * 32;
    const int nch = K >> 6;

    uint32_t smem_base = (uint32_t)__cvta_generic_to_shared(smem);

    // loaders: threads 0-127 -> A, 128-255 -> Bhi, 256-383 -> Blo (1 row each)
    const int lt = tid & 127;
    const int part = tid >> 7;               // 0:A 1:Bhi 2:Blo 3:idle
    const __half* srcP =
        part == 0 ? (A   + (size_t)(m0 + lt) * K) :
        part == 1 ? (Bhi + (size_t)(n0 + lt) * K) :
        part == 2 ? (Blo + (size_t)(n0 + lt) * K) : nullptr;
    const uint32_t tb = (uint32_t)part * 16384u;

    // prologue: chunks 0..2 -> stages 0..2
    #pragma unroll
    for (int s = 0; s < 3; s++) {
        if (part < 3 && s < nch) {
            uint32_t sb = smem_base + (uint32_t)s * STAGE_BYTES;
            cp_row128(sb + tb, srcP + s * 64, lt);
        }
        asm volatile("cp.async.commit_group;" ::: "memory");
    }

    float d[2][4][4];
    #pragma unroll
    for (int mi = 0; mi < 2; mi++)
        #pragma unroll
        for (int ni = 0; ni < 4; ni++)
            #pragma unroll
            for (int j = 0; j < 4; j++) d[mi][ni][j] = 0.f;

    const int mat = lane >> 3;
    const int rin = lane & 7;
    const int rowadd = (mat & 1) * 8 + rin;
    const int bytadd = (mat >> 1) * 16;

    for (int c = 0; c < nch; c++) {
        asm volatile("cp.async.wait_group 2;" ::: "memory");  // chunk c complete
        __syncthreads();   // all warps done with stage (c-1)%4; chunk c visible

        // issue chunk c+3 into stage (c+3)%4 (freed by compute of c-1)
        if (part < 3 && c + 3 < nch) {
            uint32_t sb = smem_base + (uint32_t)((c + 3) & 3) * STAGE_BYTES;
            cp_row128(sb + tb, srcP + ((c + 3) << 6), lt);
        }
        asm volatile("cp.async.commit_group;" ::: "memory");  // always (may be empty)

        uint32_t sb = smem_base + (uint32_t)(c & 3) * STAGE_BYTES;
        #pragma unroll
        for (int ks = 0; ks < 4; ks++) {
            const int kbyte = ks * 32 + bytadd;
            uint32_t ah[2][4];
            #pragma unroll
            for (int mi = 0; mi < 2; mi++) {
                uint32_t off = sw128((uint32_t)(wm0 + mi * 16 + rowadd) * 128u + kbyte);
                ldsm4(ah[mi], sb + off);
            }
            uint32_t bh[4][2], bl[4][2];
            #pragma unroll
            for (int np = 0; np < 2; np++) {
                uint32_t off = sw128((uint32_t)(wn0 + np * 16 + rowadd) * 128u + kbyte);
                uint32_t t4[4];
                ldsm4(t4, sb + 16384u + off);
                bh[np * 2][0]     = t4[0]; bh[np * 2][1]     = t4[2];
                bh[np * 2 + 1][0] = t4[1]; bh[np * 2 + 1][1] = t4[3];
                ldsm4(t4, sb + 32768u + off);
                bl[np * 2][0]     = t4[0]; bl[np * 2][1]     = t4[2];
                bl[np * 2 + 1][0] = t4[1]; bl[np * 2 + 1][1] = t4[3];
            }
            // term-major: 8 independent accumulators per pass
            #pragma unroll
            for (int mi = 0; mi < 2; mi++)
                #pragma unroll
                for (int ni = 0; ni < 4; ni++)
                    mma16816h(d[mi][ni], ah[mi], bh[ni]);
            #pragma unroll
            for (int mi = 0; mi < 2; mi++)
                #pragma unroll
                for (int ni = 0; ni < 4; ni++)
                    mma16816h(d[mi][ni], ah[mi], bl[ni]);
        }
    }

    // ---------------- epilogue ----------------
    const int qr = lane >> 2;
    const int qc = (lane & 3) * 2;
    #pragma unroll
    for (int mi = 0; mi < 2; mi++) {
        #pragma unroll
        for (int half = 0; half < 2; half++) {
            int m = m0 + wm0 + mi * 16 + half * 8 + qr;
            #pragma unroll
            for (int ni = 0; ni < 4; ni++) {
                int n = n0 + wn0 + ni * 8 + qc;
                float x0 = d[mi][ni][half * 2 + 0] + __ldg(bias + n + 0);
                float x1 = d[mi][ni][half * 2 + 1] + __ldg(bias + n + 1);
                if (!GELU_H) {
                    float2 o; o.x = x0; o.y = x1;
                    *(float2*)(Cf + (size_t)m * N + n) = o;
                } else {
                    x0 = 0.5f * x0 * (1.f + erff(x0 * 0.70710678118654752f));
                    x1 = 0.5f * x1 * (1.f + erff(x1 * 0.70710678118654752f));
                    __half2 p;
                    p.x = __float2half_rn(x0);
                    p.y = __float2half_rn(x1);
                    *(__half2*)(Ch + (size_t)m * N + n) = p;
                }
            }
        }
    }
}

// ---------------- fused attention (flash-style, fp32; fp16 ctx out) ----------------
// Reads packed QKV [NTOK, 2304]: Q at +0, K at +768, V at +1536.
#define ATTN_SMEM (4 * 64 * 65 * 4)
__global__ void attn_kernel(const float* __restrict__ QKV,
                            const float* __restrict__ bmask,
                            __half* __restrict__ CtxH) {
    extern __shared__ float sm[];
    float* Qs = sm;                  // [64][65]
    float* Ks = Qs + 64 * 65;
    float* Vs = Ks + 64 * 65;
    float* Ps = Vs + 64 * 65;

    int qt = blockIdx.x, bh = blockIdx.y;
    int bp = bh / H_, hd = bh % H_;
    int tx = threadIdx.x & 15, ty = threadIdx.x >> 4;
    const float scale = 0.125f;

    {
        int r = threadIdx.x >> 2;
        int cseg = (threadIdx.x & 3) * 16;
        int grow = bp * CH_ + qt * 64 + r;
        const float* gp = QKV + (size_t)grow * QKVN + hd * DH_ + cseg;
        #pragma unroll
        for (int u = 0; u < 4; u++) {
            float4 t = *(const float4*)(gp + 4 * u);
            Qs[r * 65 + cseg + 4 * u + 0] = t.x;
            Qs[r * 65 + cseg + 4 * u + 1] = t.y;
            Qs[r * 65 + cseg + 4 * u + 2] = t.z;
            Qs[r * 65 + cseg + 4 * u + 3] = t.w;
        }
    }

    float mi[4], li[4], o[4][4];
    #pragma unroll
    for (int i = 0; i < 4; i++) {
        mi[i] = -1e30f; li[i] = 0.f;
        #pragma unroll
        for (int j = 0; j < 4; j++) o[i][j] = 0.f;
    }

    for (int kt = 0; kt < CH_ / 64; kt++) {
        __syncthreads();
        {
            int r = threadIdx.x >> 2;
            int cseg = (threadIdx.x & 3) * 16;
            int grow = bp * CH_ + kt * 64 + r;
            const float* gk = QKV + (size_t)grow * QKVN + D_ + hd * DH_ + cseg;
            const float* gv = QKV + (size_t)grow * QKVN + 2 * D_ + hd * DH_ + cseg;
            #pragma unroll
            for (int u = 0; u < 4; u++) {
                float4 t = *(const float4*)(gk + 4 * u);
                Ks[r * 65 + cseg + 4 * u + 0] = t.x;
                Ks[r * 65 + cseg + 4 * u + 1] = t.y;
                Ks[r * 65 + cseg + 4 * u + 2] = t.z;
                Ks[r * 65 + cseg + 4 * u + 3] = t.w;
                float4 s = *(const float4*)(gv + 4 * u);
                Vs[r * 65 + cseg + 4 * u + 0] = s.x;
                Vs[r * 65 + cseg + 4 * u + 1] = s.y;
                Vs[r * 65 + cseg + 4 * u + 2] = s.z;
                Vs[r * 65 + cseg + 4 * u + 3] = s.w;
            }
        }
        __syncthreads();

        float biasj[4];
        #pragma unroll
        for (int j = 0; j < 4; j++) {
            float mv = bmask[bp * CH_ + kt * 64 + tx * 4 + j];
            biasj[j] = (1.f - mv) * -10000.f;
        }

        float s[4][4] = {};
        #pragma unroll 8
        for (int dd = 0; dd < 64; dd++) {
            float av[4], bv[4];
            #pragma unroll
            for (int i = 0; i < 4; i++) av[i] = Qs[(ty * 4 + i) * 65 + dd];
            #pragma unroll
            for (int j = 0; j < 4; j++) bv[j] = Ks[(tx * 4 + j) * 65 + dd];
            #pragma unroll
            for (int i = 0; i < 4; i++)
                #pragma unroll
                for (int j = 0; j < 4; j++)
                    s[i][j] = fmaf(av[i], bv[j], s[i][j]);
        }
        #pragma unroll
        for (int i = 0; i < 4; i++)
            #pragma unroll
            for (int j = 0; j < 4; j++)
                s[i][j] = s[i][j] * scale + biasj[j];

        float p[4][4];
        #pragma unroll
        for (int i = 0; i < 4; i++) {
            float rm = fmaxf(fmaxf(s[i][0], s[i][1]), fmaxf(s[i][2], s[i][3]));
            #pragma unroll
            for (int off = 1; off <= 8; off <<= 1)
                rm = fmaxf(rm, __shfl_xor_sync(0xffffffffu, rm, off));
            float mnew = fmaxf(mi[i], rm);
            float c = __expf(mi[i] - mnew);
            float rs = 0.f;
            #pragma unroll
            for (int j = 0; j < 4; j++) { p[i][j] = __expf(s[i][j] - mnew); rs += p[i][j]; }
            #pragma unroll
            for (int off = 1; off <= 8; off <<= 1)
                rs += __shfl_xor_sync(0xffffffffu, rs, off);
            li[i] = li[i] * c + rs;
            mi[i] = mnew;
            #pragma unroll
            for (int j = 0; j < 4; j++) o[i][j] *= c;
        }

        #pragma unroll
        for (int i = 0; i < 4; i++)
            #pragma unroll
            for (int j = 0; j < 4; j++)
                Ps[(ty * 4 + i) * 65 + tx * 4 + j] = p[i][j];
        __syncthreads();

        #pragma unroll 8
        for (int kk = 0; kk < 64; kk++) {
            float av[4], bv[4];
            #pragma unroll
            for (int i = 0; i < 4; i++) av[i] = Ps[(ty * 4 + i) * 65 + kk];
            #pragma unroll
            for (int j = 0; j < 4; j++) bv[j] = Vs[kk * 65 + tx * 4 + j];
            #pragma unroll
            for (int i = 0; i < 4; i++)
                #pragma unroll
                for (int j = 0; j < 4; j++)
                    o[i][j] = fmaf(av[i], bv[j], o[i][j]);
        }
    }

    #pragma unroll
    for (int i = 0; i < 4; i++) {
        float inv = 1.f / li[i];
        int grow = bp * CH_ + qt * 64 + ty * 4 + i;
        size_t base = (size_t)grow * D_ + hd * DH_ + tx * 4;
        #pragma unroll
        for (int j = 0; j < 4; j++)
            CtxH[base + j] = __float2half_rn(o[i][j] * inv);
    }
}

// ---------------- offset mean pooling ----------------
__global__ void pool_kernel(const float* __restrict__ emb,
                            const int* __restrict__ offset,
                            const int* __restrict__ xmask,
                            float* __restrict__ out) {
    int w = blockIdx.x, b = blockIdx.y;
    int st = offset[((size_t)b * W_ + w) * 2 + 0];
    int ed = offset[((size_t)b * W_ + w) * 2 + 1];
    bool valid = (xmask[b * W_ + w] != 0) && (st < ed);
    float acc[3] = {0.f, 0.f, 0.f};
    if (valid) {
        for (int s = st; s < ed; s++) {
            const float* rp = emb + ((size_t)b * S_ + s) * D_;
            #pragma unroll
            for (int i = 0; i < 3; i++) acc[i] += rp[i * 256 + threadIdx.x];
        }
    }
    float inv = valid ? 1.f / fmaxf((float)(ed - st), 1.f) : 0.f;
    float* op = out + ((size_t)b * W_ + w) * D_;
    #pragma unroll
    for (int i = 0; i < 3; i++) op[i * 256 + threadIdx.x] = acc[i] * inv;
}

// ---------------- launcher ----------------
extern "C" void kernel_launch(void* const* d_in, const int* in_sizes, int n_in,
                              void* d_out, int out_size) {
    const int*   x_bert   = (const int*)  d_in[0];
    const float* x_mask_f = (const float*)d_in[1];
    const int*   x_off    = (const int*)  d_in[2];
    const int*   x_wmask  = (const int*)  d_in[3];
    const float* word_emb = (const float*)d_in[4];
    const float* pos_emb  = (const float*)d_in[5];
    const float* type_emb = (const float*)d_in[6];
    const float* emb_g    = (const float*)d_in[7];
    const float* emb_b    = (const float*)d_in[8];
    const float* Wq = (const float*)d_in[9];   const float* bq = (const float*)d_in[10];
    const float* Wk = (const float*)d_in[11];  const float* bk = (const float*)d_in[12];
    const float* Wv = (const float*)d_in[13];  const float* bv = (const float*)d_in[14];
    const float* Wo = (const float*)d_in[15];  const float* bo = (const float*)d_in[16];
    const float* ln1_g = (const float*)d_in[17]; const float* ln1_b = (const float*)d_in[18];
    const float* W1 = (const float*)d_in[19];  const float* b1f = (const float*)d_in[20];
    const float* W2 = (const float*)d_in[21];  const float* b2f = (const float*)d_in[22];
    const float* ln2_g = (const float*)d_in[23]; const float* ln2_b = (const float*)d_in[24];
    float* out = (float*)d_out;

    float *h, *h1, *tmp, *qkv, *bqkv;
    __half *hh, *h1h, *ctxh, *midh, *wthi, *wtlo;
    cudaGetSymbolAddress((void**)&h,    g_h);
    cudaGetSymbolAddress((void**)&h1,   g_h1);
    cudaGetSymbolAddress((void**)&tmp,  g_tmp);
    cudaGetSymbolAddress((void**)&qkv,  g_qkv);
    cudaGetSymbolAddress((void**)&bqkv, g_bqkv);
    cudaGetSymbolAddress((void**)&hh,   g_hh);
    cudaGetSymbolAddress((void**)&h1h,  g_h1h);
    cudaGetSymbolAddress((void**)&ctxh, g_ctxh);
    cudaGetSymbolAddress((void**)&midh, g_midh);
    cudaGetSymbolAddress((void**)&wthi, g_wthi);
    cudaGetSymbolAddress((void**)&wtlo, g_wtlo);

    cudaFuncSetAttribute(attn_kernel, cudaFuncAttributeMaxDynamicSharedMemorySize, ATTN_SMEM);
    cudaFuncSetAttribute(gemm_tc<false>, cudaFuncAttributeMaxDynamicSharedMemorySize, GEMM_SMEM);
    cudaFuncSetAttribute(gemm_tc<true>,  cudaFuncAttributeMaxDynamicSharedMemorySize, GEMM_SMEM);

    // (0) weight prep: ONE launch for all layers/matrices; (1) bias pack
    wprep_all<<<L_ * WPREP_PER_LAYER, dim3(32, 8)>>>(Wq, Wk, Wv, Wo, W1, W2, wthi, wtlo);
    biaspack_kernel<<<dim3(3, L_), D_>>>(bq, bk, bv, bqkv);

    // (2) embedding + LN
    embed_ln_kernel<<<NTOK, 256>>>(x_bert, word_emb, pos_emb, type_emb, emb_g, emb_b, h, hh);

    dim3 gQKV(QKVN / 128, NTOK / 128);  // (18, 64)
    dim3 gD(D_ / 128, NTOK / 128);      // (6, 64)
    dim3 gF(F_ / 128, NTOK / 128);      // (24, 64)

    for (int l = 0; l < L_; l++) {
        size_t wb = (size_t)l * WSTRIDE;

        // fused QKV GEMM: N = 2304
        gemm_tc<false><<<gQKV, 512, GEMM_SMEM>>>(hh, wthi + wb, wtlo + wb,
                                                 bqkv + (size_t)l * QKVN, qkv,
                                                 nullptr, NTOK, QKVN, D_);

        attn_kernel<<<dim3(CH_ / 64, NSEQ * H_), 256, ATTN_SMEM>>>(qkv, x_mask_f, ctxh);

        gemm_tc<false><<<gD, 512, GEMM_SMEM>>>(ctxh, wthi + wb + WOFF_O, wtlo + wb + WOFF_O,
                                               bo + l * D_, tmp, nullptr, NTOK, D_, D_);
        ln_res_kernel<<<NTOK, 256>>>(h, tmp, ln1_g + l * D_, ln1_b + l * D_, h1, h1h);

        gemm_tc<true><<<gF, 512, GEMM_SMEM>>>(h1h, wthi + wb + WOFF_1, wtlo + wb + WOFF_1,
                                              b1f + l * F_, nullptr, midh, NTOK, F_, D_);
        gemm_tc<false><<<gD, 512, GEMM_SMEM>>>(midh, wthi + wb + WOFF_2, wtlo + wb + WOFF_2,
                                               b2f + l * D_, tmp, nullptr, NTOK, D_, F_);
        ln_res_kernel<<<NTOK, 256>>>(h1, tmp, ln2_g + l * D_, ln2_b + l * D_, h, hh);
    }

    pool_kernel<<<dim3(W_, B_), 256>>>(h, x_off, x_wmask, out);
}

// round 15
// speedup vs baseline: 1.5415x; 1.5415x over previous
#include <cuda_runtime.h>
#include <cuda_fp16.h>
#include <math.h>
#include <stdint.h>

// ---------------- problem constants ----------------
#define D_    768
#define H_    12
#define DH_   64
#define F_    3072
#define L_    4
#define CH_   512
#define NSEQ  16              // B * (S/CH)
#define NTOK  (NSEQ * CH_)    // 8192
#define B_    8
#define S_    1024
#define W_    512
#define LNEPS 1e-12f
#define QKVN  (3 * D_)        // 2304

// weight layout offsets within per-layer block (transposed [N,K] fp16 hi/lo)
#define WOFF_Q  0
#define WOFF_O  (3*D_*D_)
#define WOFF_1  (4*D_*D_)            // [N=F, K=D]
#define WOFF_2  (4*D_*D_ + D_*F_)    // [N=D, K=F]
#define WSTRIDE (4*D_*D_ + 2*D_*F_)

// ---------------- scratch (device globals; no allocs allowed) ----------------
__device__ float g_h  [NTOK * D_];
__device__ float g_h1 [NTOK * D_];
__device__ float g_tmp[NTOK * D_];
__device__ float g_qkv[NTOK * QKVN];
__device__ float g_bqkv[L_ * QKVN];

__device__ __half g_hh  [NTOK * D_];   // activations: SINGLE fp16
__device__ __half g_h1h [NTOK * D_];
__device__ __half g_ctxh[NTOK * D_];
__device__ __half g_midh[NTOK * F_];
__device__ __half g_wthi[L_ * WSTRIDE];  // weights: fp16 hi + lo (exact to 2^-22)
__device__ __half g_wtlo[L_ * WSTRIDE];

// ---------------- helpers ----------------
__device__ __forceinline__ void split_fp16(float x, __half& hi, __half& lo) {
    hi = __float2half_rn(x);
    lo = __float2half_rn(x - __half2float(hi));
}

__device__ __forceinline__ float block_sum_256(float val, float* red) {
    int lane = threadIdx.x & 31, warp = threadIdx.x >> 5;
    #pragma unroll
    for (int o = 16; o > 0; o >>= 1) val += __shfl_xor_sync(0xffffffffu, val, o);
    if (lane == 0) red[warp] = val;
    __syncthreads();
    if (warp == 0) {
        float t = (lane < 8) ? red[lane] : 0.f;
        #pragma unroll
        for (int o = 4; o > 0; o >>= 1) t += __shfl_xor_sync(0xffffffffu, t, o);
        if (lane == 0) red[0] = t;
    }
    __syncthreads();
    float r = red[0];
    __syncthreads();
    return r;
}

// ---------------- batched weight transpose + fp16 split ----------------
#define WPREP_PER_LAYER 6912
__global__ void wprep_all(const float* __restrict__ Wq, const float* __restrict__ Wk,
                          const float* __restrict__ Wv, const float* __restrict__ Wo,
                          const float* __restrict__ W1, const float* __restrict__ W2,
                          __half* __restrict__ Thi,
                          __half* __restrict__ Tlo) {
    __shared__ float t[32][33];
    int id = blockIdx.x;
    int l = id / WPREP_PER_LAYER;
    int r = id % WPREP_PER_LAYER;

    const float* src;
    size_t doff = (size_t)l * WSTRIDE;
    int K, N, cols, local;
    if (r < 2304) {
        int mat = r / 576; local = r % 576;
        K = D_; N = D_; cols = 24;
        src = (mat == 0 ? Wq : mat == 1 ? Wk : mat == 2 ? Wv : Wo) + (size_t)l * D_ * D_;
        doff += (size_t)mat * D_ * D_;
    } else if (r < 4608) {
        local = r - 2304;
        K = D_; N = F_; cols = 96;
        src = W1 + (size_t)l * D_ * F_;
        doff += WOFF_1;
    } else {
        local = r - 4608;
        K = F_; N = D_; cols = 24;
        src = W2 + (size_t)l * F_ * D_;
        doff += WOFF_2;
    }
    int nb = (local % cols) * 32, kb = (local / cols) * 32;

    int tx = threadIdx.x, ty = threadIdx.y;
    #pragma unroll
    for (int i = 0; i < 4; i++)
        t[ty + 8 * i][tx] = src[(size_t)(kb + ty + 8 * i) * N + nb + tx];
    __syncthreads();
    #pragma unroll
    for (int i = 0; i < 4; i++) {
        float x = t[tx][ty + 8 * i];
        __half hi, lo;
        split_fp16(x, hi, lo);
        size_t o = doff + (size_t)(nb + ty + 8 * i) * K + kb + tx;
        Thi[o] = hi;
        Tlo[o] = lo;
    }
}

// pack [bq;bk;bv] per layer into contiguous 2304-vector
__global__ void biaspack_kernel(const float* __restrict__ bq,
                                const float* __restrict__ bk,
                                const float* __restrict__ bv,
                                float* __restrict__ dst) {
    int mat = blockIdx.x, l = blockIdx.y;
    const float* s = (mat == 0 ? bq : mat == 1 ? bk : bv) + l * D_;
    dst[(size_t)l * QKVN + mat * D_ + threadIdx.x] = s[threadIdx.x];
}

// ---------------- fused embedding + LayerNorm (+ fp16 out) ----------------
__global__ void embed_ln_kernel(const int* __restrict__ ids,
                                const float* __restrict__ we,
                                const float* __restrict__ pe,
                                const float* __restrict__ te,
                                const float* __restrict__ g,
                                const float* __restrict__ b,
                                float* __restrict__ out,
                                __half* __restrict__ oh) {
    __shared__ float red[32];
    int row = blockIdx.x;
    int pos = row % CH_;
    int id  = ids[row];
    float v[3];
    float s = 0.f;
    #pragma unroll
    for (int i = 0; i < 3; i++) {
        int d = i * 256 + threadIdx.x;
        v[i] = we[(size_t)id * D_ + d] + pe[pos * D_ + d] + te[d];
        s += v[i];
    }
    float mu = block_sum_256(s, red) * (1.f / D_);
    float sq = 0.f;
    #pragma unroll
    for (int i = 0; i < 3; i++) { float t = v[i] - mu; sq += t * t; }
    float rstd = rsqrtf(block_sum_256(sq, red) * (1.f / D_) + LNEPS);
    #pragma unroll
    for (int i = 0; i < 3; i++) {
        int d = i * 256 + threadIdx.x;
        float y = (v[i] - mu) * rstd * g[d] + b[d];
        size_t idx = (size_t)row * D_ + d;
        out[idx] = y;
        oh[idx] = __float2half_rn(y);
    }
}

// ---------------- residual + LayerNorm (+ fp16 out) ----------------
__global__ void ln_res_kernel(const float* __restrict__ X,
                              const float* __restrict__ Y,
                              const float* __restrict__ g,
                              const float* __restrict__ b,
                              float* __restrict__ out,
                              __half* __restrict__ oh) {
    __shared__ float red[32];
    int row = blockIdx.x;
    float v[3];
    float s = 0.f;
    #pragma unroll
    for (int i = 0; i < 3; i++) {
        int d = i * 256 + threadIdx.x;
        size_t idx = (size_t)row * D_ + d;
        v[i] = X[idx] + Y[idx];
        s += v[i];
    }
    float mu = block_sum_256(s, red) * (1.f / D_);
    float sq = 0.f;
    #pragma unroll
    for (int i = 0; i < 3; i++) { float t = v[i] - mu; sq += t * t; }
    float rstd = rsqrtf(block_sum_256(sq, red) * (1.f / D_) + LNEPS);
    #pragma unroll
    for (int i = 0; i < 3; i++) {
        int d = i * 256 + threadIdx.x;
        float y = (v[i] - mu) * rstd * g[d] + b[d];
        size_t idx = (size_t)row * D_ + d;
        out[idx] = y;
        oh[idx] = __float2half_rn(y);
    }
}

// ============================================================================
// fp16x2 tensor-core GEMM via mma.sync.m16n8k16.f32.f16.f16.f32:
// C[M,N] = A_fp16[M,K] @ (Bh + Bl)^T (B stored [N,K]) + bias.
// CTA tile 256x128 (2x the outputs per copied byte vs 128x128 — the GEMM is
// LDGSTS-issue-bound at rt=8cyc/SMSP, so copy amortization is the win).
// K-chunk 64, 3-stage cp.async pipeline: stage = A 32KB + Bh 16KB + Bl 16KB
// = 64KB, 3 stages = 192KB. 512 threads = 16 warps (4m x 4n), warp tile 64x32.
// ============================================================================
#define GSTAGES 3
#define STAGE_BYTES 65536u               // A 32KB | Bh 16KB | Bl 16KB
#define GEMM_SMEM (GSTAGES * 65536)      // 192KB

__device__ __forceinline__ void ldsm4(uint32_t* r, uint32_t addr) {
    asm volatile("ldmatrix.sync.aligned.m8n8.x4.shared.b16 {%0,%1,%2,%3}, [%4];"
                 : "=r"(r[0]), "=r"(r[1]), "=r"(r[2]), "=r"(r[3]) : "r"(addr));
}

__device__ __forceinline__ void mma16816h(float* d, const uint32_t* a, const uint32_t* b) {
    asm volatile(
        "mma.sync.aligned.m16n8k16.row.col.f32.f16.f16.f32 "
        "{%0,%1,%2,%3}, {%4,%5,%6,%7}, {%8,%9}, {%0,%1,%2,%3};"
        : "+f"(d[0]), "+f"(d[1]), "+f"(d[2]), "+f"(d[3])
        : "r"(a[0]), "r"(a[1]), "r"(a[2]), "r"(a[3]), "r"(b[0]), "r"(b[1]));
}

__device__ __forceinline__ uint32_t sw128(uint32_t off) {
    return off ^ ((off >> 3) & 0x70);
}

__device__ __forceinline__ void cp_row128(uint32_t sdst_base, const __half* src, int row) {
    #pragma unroll
    for (int i = 0; i < 8; i++) {
        uint32_t off = (uint32_t)row * 128u + (uint32_t)i * 16u;
        uint32_t d = sdst_base + sw128(off);
        asm volatile("cp.async.cg.shared.global [%0], [%1], 16;"
                     :: "r"(d), "l"(src + i * 8) : "memory");
    }
}

template <bool GELU_H>
__global__ void __launch_bounds__(512)
gemm_tc(const __half* __restrict__ A,
        const __half* __restrict__ Bhi, const __half* __restrict__ Blo,
        const float* __restrict__ bias,
        float* __restrict__ Cf,
        __half* __restrict__ Ch,
        int M, int N, int K) {
    extern __shared__ char smem[];
    const int tid = threadIdx.x;
    const int wid = tid >> 5, lane = tid & 31;
    const int m0 = blockIdx.y * 256, n0 = blockIdx.x * 128;
    const int wm0 = (wid & 3) * 64;          // warp m offset (4 x 64 = 256)
    const int wn0 = (wid >> 2) * 32;         // warp n offset (4 x 32 = 128)
    const int nch = K >> 6;

    uint32_t smem_base = (uint32_t)__cvta_generic_to_shared(smem);

    // loaders: 512 threads, one 128B row each.
    // tid 0-255   -> A rows 0-255      (region 0,     32KB)
    // tid 256-383 -> Bhi rows 0-127    (region 32768, 16KB)
    // tid 384-511 -> Blo rows 0-127    (region 49152, 16KB)
    const __half* srcP;
    uint32_t tb;
    int lrow;
    if (tid < 256)      { lrow = tid;       srcP = A   + (size_t)(m0 + lrow) * K; tb = 0u; }
    else if (tid < 384) { lrow = tid - 256; srcP = Bhi + (size_t)(n0 + lrow) * K; tb = 32768u; }
    else                { lrow = tid - 384; srcP = Blo + (size_t)(n0 + lrow) * K; tb = 49152u; }

    // prologue: stages 0 and 1 (chunks 0, 1)
    #pragma unroll
    for (int s = 0; s < 2; s++) {
        uint32_t sb = smem_base + (uint32_t)s * STAGE_BYTES;
        cp_row128(sb + tb, srcP + s * 64, lrow);
        asm volatile("cp.async.commit_group;" ::: "memory");
    }

    float d[4][4][4];
    #pragma unroll
    for (int mi = 0; mi < 4; mi++)
        #pragma unroll
        for (int ni = 0; ni < 4; ni++)
            #pragma unroll
            for (int j = 0; j < 4; j++) d[mi][ni][j] = 0.f;

    const int mat = lane >> 3;
    const int rin = lane & 7;
    const int rowadd = (mat & 1) * 8 + rin;
    const int bytadd = (mat >> 1) * 16;

    int stage = 0;
    for (int c = 0; c < nch; c++) {
        if (c == nch - 1) {
            asm volatile("cp.async.wait_group 0;" ::: "memory");
        } else {
            asm volatile("cp.async.wait_group 1;" ::: "memory");
        }
        __syncthreads();   // chunk c ready; all warps done with previous stage reuse

        // issue chunk c+2 into the stage just freed
        if (c + 2 < nch) {
            int s2 = stage + 2; if (s2 >= GSTAGES) s2 -= GSTAGES;
            uint32_t sb = smem_base + (uint32_t)s2 * STAGE_BYTES;
            cp_row128(sb + tb, srcP + ((c + 2) << 6), lrow);
            asm volatile("cp.async.commit_group;" ::: "memory");
        }

        uint32_t sb = smem_base + (uint32_t)stage * STAGE_BYTES;
        #pragma unroll
        for (int ks = 0; ks < 4; ks++) {
            const int kbyte = ks * 32 + bytadd;
            // A fragments: 4 m-subtiles of 16
            uint32_t ah[4][4];
            #pragma unroll
            for (int mi = 0; mi < 4; mi++) {
                uint32_t off = sw128((uint32_t)(wm0 + mi * 16 + rowadd) * 128u + kbyte);
                ldsm4(ah[mi], sb + off);
            }
            // hi term
            {
                uint32_t bfr[4][2];
                #pragma unroll
                for (int np = 0; np < 2; np++) {
                    uint32_t off = sw128((uint32_t)(wn0 + np * 16 + rowadd) * 128u + kbyte);
                    uint32_t t4[4];
                    ldsm4(t4, sb + 32768u + off);
                    bfr[np * 2][0]     = t4[0]; bfr[np * 2][1]     = t4[2];
                    bfr[np * 2 + 1][0] = t4[1]; bfr[np * 2 + 1][1] = t4[3];
                }
                #pragma unroll
                for (int mi = 0; mi < 4; mi++)
                    #pragma unroll
                    for (int ni = 0; ni < 4; ni++)
                        mma16816h(d[mi][ni], ah[mi], bfr[ni]);
            }
            // lo term
            {
                uint32_t bfr[4][2];
                #pragma unroll
                for (int np = 0; np < 2; np++) {
                    uint32_t off = sw128((uint32_t)(wn0 + np * 16 + rowadd) * 128u + kbyte);
                    uint32_t t4[4];
                    ldsm4(t4, sb + 49152u + off);
                    bfr[np * 2][0]     = t4[0]; bfr[np * 2][1]     = t4[2];
                    bfr[np * 2 + 1][0] = t4[1]; bfr[np * 2 + 1][1] = t4[3];
                }
                #pragma unroll
                for (int mi = 0; mi < 4; mi++)
                    #pragma unroll
                    for (int ni = 0; ni < 4; ni++)
                        mma16816h(d[mi][ni], ah[mi], bfr[ni]);
            }
        }
        stage = stage + 1; if (stage >= GSTAGES) stage = 0;
    }

    // ---------------- epilogue ----------------
    const int qr = lane >> 2;
    const int qc = (lane & 3) * 2;
    #pragma unroll
    for (int mi = 0; mi < 4; mi++) {
        #pragma unroll
        for (int half = 0; half < 2; half++) {
            int m = m0 + wm0 + mi * 16 + half * 8 + qr;
            #pragma unroll
            for (int ni = 0; ni < 4; ni++) {
                int n = n0 + wn0 + ni * 8 + qc;
                float x0 = d[mi][ni][half * 2 + 0] + __ldg(bias + n + 0);
                float x1 = d[mi][ni][half * 2 + 1] + __ldg(bias + n + 1);
                if (!GELU_H) {
                    float2 o; o.x = x0; o.y = x1;
                    *(float2*)(Cf + (size_t)m * N + n) = o;
                } else {
                    x0 = 0.5f * x0 * (1.f + erff(x0 * 0.70710678118654752f));
                    x1 = 0.5f * x1 * (1.f + erff(x1 * 0.70710678118654752f));
                    __half2 p;
                    p.x = __float2half_rn(x0);
                    p.y = __float2half_rn(x1);
                    *(__half2*)(Ch + (size_t)m * N + n) = p;
                }
            }
        }
    }
}

// ---------------- fused attention (flash-style, fp32; fp16 ctx out) ----------------
// Reads packed QKV [NTOK, 2304]: Q at +0, K at +768, V at +1536.
#define ATTN_SMEM (4 * 64 * 65 * 4)
__global__ void attn_kernel(const float* __restrict__ QKV,
                            const float* __restrict__ bmask,
                            __half* __restrict__ CtxH) {
    extern __shared__ float sm[];
    float* Qs = sm;                  // [64][65]
    float* Ks = Qs + 64 * 65;
    float* Vs = Ks + 64 * 65;
    float* Ps = Vs + 64 * 65;

    int qt = blockIdx.x, bh = blockIdx.y;
    int bp = bh / H_, hd = bh % H_;
    int tx = threadIdx.x & 15, ty = threadIdx.x >> 4;
    const float scale = 0.125f;

    {
        int r = threadIdx.x >> 2;
        int cseg = (threadIdx.x & 3) * 16;
        int grow = bp * CH_ + qt * 64 + r;
        const float* gp = QKV + (size_t)grow * QKVN + hd * DH_ + cseg;
        #pragma unroll
        for (int u = 0; u < 4; u++) {
            float4 t = *(const float4*)(gp + 4 * u);
            Qs[r * 65 + cseg + 4 * u + 0] = t.x;
            Qs[r * 65 + cseg + 4 * u + 1] = t.y;
            Qs[r * 65 + cseg + 4 * u + 2] = t.z;
            Qs[r * 65 + cseg + 4 * u + 3] = t.w;
        }
    }

    float mi[4], li[4], o[4][4];
    #pragma unroll
    for (int i = 0; i < 4; i++) {
        mi[i] = -1e30f; li[i] = 0.f;
        #pragma unroll
        for (int j = 0; j < 4; j++) o[i][j] = 0.f;
    }

    for (int kt = 0; kt < CH_ / 64; kt++) {
        __syncthreads();
        {
            int r = threadIdx.x >> 2;
            int cseg = (threadIdx.x & 3) * 16;
            int grow = bp * CH_ + kt * 64 + r;
            const float* gk = QKV + (size_t)grow * QKVN + D_ + hd * DH_ + cseg;
            const float* gv = QKV + (size_t)grow * QKVN + 2 * D_ + hd * DH_ + cseg;
            #pragma unroll
            for (int u = 0; u < 4; u++) {
                float4 t = *(const float4*)(gk + 4 * u);
                Ks[r * 65 + cseg + 4 * u + 0] = t.x;
                Ks[r * 65 + cseg + 4 * u + 1] = t.y;
                Ks[r * 65 + cseg + 4 * u + 2] = t.z;
                Ks[r * 65 + cseg + 4 * u + 3] = t.w;
                float4 s = *(const float4*)(gv + 4 * u);
                Vs[r * 65 + cseg + 4 * u + 0] = s.x;
                Vs[r * 65 + cseg + 4 * u + 1] = s.y;
                Vs[r * 65 + cseg + 4 * u + 2] = s.z;
                Vs[r * 65 + cseg + 4 * u + 3] = s.w;
            }
        }
        __syncthreads();

        float biasj[4];
        #pragma unroll
        for (int j = 0; j < 4; j++) {
            float mv = bmask[bp * CH_ + kt * 64 + tx * 4 + j];
            biasj[j] = (1.f - mv) * -10000.f;
        }

        float s[4][4] = {};
        #pragma unroll 8
        for (int dd = 0; dd < 64; dd++) {
            float av[4], bv[4];
            #pragma unroll
            for (int i = 0; i < 4; i++) av[i] = Qs[(ty * 4 + i) * 65 + dd];
            #pragma unroll
            for (int j = 0; j < 4; j++) bv[j] = Ks[(tx * 4 + j) * 65 + dd];
            #pragma unroll
            for (int i = 0; i < 4; i++)
                #pragma unroll
                for (int j = 0; j < 4; j++)
                    s[i][j] = fmaf(av[i], bv[j], s[i][j]);
        }
        #pragma unroll
        for (int i = 0; i < 4; i++)
            #pragma unroll
            for (int j = 0; j < 4; j++)
                s[i][j] = s[i][j] * scale + biasj[j];

        float p[4][4];
        #pragma unroll
        for (int i = 0; i < 4; i++) {
            float rm = fmaxf(fmaxf(s[i][0], s[i][1]), fmaxf(s[i][2], s[i][3]));
            #pragma unroll
            for (int off = 1; off <= 8; off <<= 1)
                rm = fmaxf(rm, __shfl_xor_sync(0xffffffffu, rm, off));
            float mnew = fmaxf(mi[i], rm);
            float c = __expf(mi[i] - mnew);
            float rs = 0.f;
            #pragma unroll
            for (int j = 0; j < 4; j++) { p[i][j] = __expf(s[i][j] - mnew); rs += p[i][j]; }
            #pragma unroll
            for (int off = 1; off <= 8; off <<= 1)
                rs += __shfl_xor_sync(0xffffffffu, rs, off);
            li[i] = li[i] * c + rs;
            mi[i] = mnew;
            #pragma unroll
            for (int j = 0; j < 4; j++) o[i][j] *= c;
        }

        #pragma unroll
        for (int i = 0; i < 4; i++)
            #pragma unroll
            for (int j = 0; j < 4; j++)
                Ps[(ty * 4 + i) * 65 + tx * 4 + j] = p[i][j];
        __syncthreads();

        #pragma unroll 8
        for (int kk = 0; kk < 64; kk++) {
            float av[4], bv[4];
            #pragma unroll
            for (int i = 0; i < 4; i++) av[i] = Ps[(ty * 4 + i) * 65 + kk];
            #pragma unroll
            for (int j = 0; j < 4; j++) bv[j] = Vs[kk * 65 + tx * 4 + j];
            #pragma unroll
            for (int i = 0; i < 4; i++)
                #pragma unroll
                for (int j = 0; j < 4; j++)
                    o[i][j] = fmaf(av[i], bv[j], o[i][j]);
        }
    }

    #pragma unroll
    for (int i = 0; i < 4; i++) {
        float inv = 1.f / li[i];
        int grow = bp * CH_ + qt * 64 + ty * 4 + i;
        size_t base = (size_t)grow * D_ + hd * DH_ + tx * 4;
        #pragma unroll
        for (int j = 0; j < 4; j++)
            CtxH[base + j] = __float2half_rn(o[i][j] * inv);
    }
}

// ---------------- offset mean pooling ----------------
__global__ void pool_kernel(const float* __restrict__ emb,
                            const int* __restrict__ offset,
                            const int* __restrict__ xmask,
                            float* __restrict__ out) {
    int w = blockIdx.x, b = blockIdx.y;
    int st = offset[((size_t)b * W_ + w) * 2 + 0];
    int ed = offset[((size_t)b * W_ + w) * 2 + 1];
    bool valid = (xmask[b * W_ + w] != 0) && (st < ed);
    float acc[3] = {0.f, 0.f, 0.f};
    if (valid) {
        for (int s = st; s < ed; s++) {
            const float* rp = emb + ((size_t)b * S_ + s) * D_;
            #pragma unroll
            for (int i = 0; i < 3; i++) acc[i] += rp[i * 256 + threadIdx.x];
        }
    }
    float inv = valid ? 1.f / fmaxf((float)(ed - st), 1.f) : 0.f;
    float* op = out + ((size_t)b * W_ + w) * D_;
    #pragma unroll
    for (int i = 0; i < 3; i++) op[i * 256 + threadIdx.x] = acc[i] * inv;
}

// ---------------- launcher ----------------
extern "C" void kernel_launch(void* const* d_in, const int* in_sizes, int n_in,
                              void* d_out, int out_size) {
    const int*   x_bert   = (const int*)  d_in[0];
    const float* x_mask_f = (const float*)d_in[1];
    const int*   x_off    = (const int*)  d_in[2];
    const int*   x_wmask  = (const int*)  d_in[3];
    const float* word_emb = (const float*)d_in[4];
    const float* pos_emb  = (const float*)d_in[5];
    const float* type_emb = (const float*)d_in[6];
    const float* emb_g    = (const float*)d_in[7];
    const float* emb_b    = (const float*)d_in[8];
    const float* Wq = (const float*)d_in[9];   const float* bq = (const float*)d_in[10];
    const float* Wk = (const float*)d_in[11];  const float* bk = (const float*)d_in[12];
    const float* Wv = (const float*)d_in[13];  const float* bv = (const float*)d_in[14];
    const float* Wo = (const float*)d_in[15];  const float* bo = (const float*)d_in[16];
    const float* ln1_g = (const float*)d_in[17]; const float* ln1_b = (const float*)d_in[18];
    const float* W1 = (const float*)d_in[19];  const float* b1f = (const float*)d_in[20];
    const float* W2 = (const float*)d_in[21];  const float* b2f = (const float*)d_in[22];
    const float* ln2_g = (const float*)d_in[23]; const float* ln2_b = (const float*)d_in[24];
    float* out = (float*)d_out;

    float *h, *h1, *tmp, *qkv, *bqkv;
    __half *hh, *h1h, *ctxh, *midh, *wthi, *wtlo;
    cudaGetSymbolAddress((void**)&h,    g_h);
    cudaGetSymbolAddress((void**)&h1,   g_h1);
    cudaGetSymbolAddress((void**)&tmp,  g_tmp);
    cudaGetSymbolAddress((void**)&qkv,  g_qkv);
    cudaGetSymbolAddress((void**)&bqkv, g_bqkv);
    cudaGetSymbolAddress((void**)&hh,   g_hh);
    cudaGetSymbolAddress((void**)&h1h,  g_h1h);
    cudaGetSymbolAddress((void**)&ctxh, g_ctxh);
    cudaGetSymbolAddress((void**)&midh, g_midh);
    cudaGetSymbolAddress((void**)&wthi, g_wthi);
    cudaGetSymbolAddress((void**)&wtlo, g_wtlo);

    cudaFuncSetAttribute(attn_kernel, cudaFuncAttributeMaxDynamicSharedMemorySize, ATTN_SMEM);
    cudaFuncSetAttribute(gemm_tc<false>, cudaFuncAttributeMaxDynamicSharedMemorySize, GEMM_SMEM);
    cudaFuncSetAttribute(gemm_tc<true>,  cudaFuncAttributeMaxDynamicSharedMemorySize, GEMM_SMEM);

    // (0) weight prep: ONE launch for all layers/matrices; (1) bias pack
    wprep_all<<<L_ * WPREP_PER_LAYER, dim3(32, 8)>>>(Wq, Wk, Wv, Wo, W1, W2, wthi, wtlo);
    biaspack_kernel<<<dim3(3, L_), D_>>>(bq, bk, bv, bqkv);

    // (2) embedding + LN
    embed_ln_kernel<<<NTOK, 256>>>(x_bert, word_emb, pos_emb, type_emb, emb_g, emb_b, h, hh);

    dim3 gQKV(QKVN / 128, NTOK / 256);  // (18, 32)
    dim3 gD(D_ / 128, NTOK / 256);      // (6, 32)
    dim3 gF(F_ / 128, NTOK / 256);      // (24, 32)

    for (int l = 0; l < L_; l++) {
        size_t wb = (size_t)l * WSTRIDE;

        // fused QKV GEMM: N = 2304
        gemm_tc<false><<<gQKV, 512, GEMM_SMEM>>>(hh, wthi + wb, wtlo + wb,
                                                 bqkv + (size_t)l * QKVN, qkv,
                                                 nullptr, NTOK, QKVN, D_);

        attn_kernel<<<dim3(CH_ / 64, NSEQ * H_), 256, ATTN_SMEM>>>(qkv, x_mask_f, ctxh);

        gemm_tc<false><<<gD, 512, GEMM_SMEM>>>(ctxh, wthi + wb + WOFF_O, wtlo + wb + WOFF_O,
                                               bo + l * D_, tmp, nullptr, NTOK, D_, D_);
        ln_res_kernel<<<NTOK, 256>>>(h, tmp, ln1_g + l * D_, ln1_b + l * D_, h1, h1h);

        gemm_tc<true><<<gF, 512, GEMM_SMEM>>>(h1h, wthi + wb + WOFF_1, wtlo + wb + WOFF_1,
                                              b1f + l * F_, nullptr, midh, NTOK, F_, D_);
        gemm_tc<false><<<gD, 512, GEMM_SMEM>>>(midh, wthi + wb + WOFF_2, wtlo + wb + WOFF_2,
                                               b2f + l * D_, tmp, nullptr, NTOK, D_, F_);
        ln_res_kernel<<<NTOK, 256>>>(h1, tmp, ln2_g + l * D_, ln2_b + l * D_, h, hh);
    }

    pool_kernel<<<dim3(W_, B_), 256>>>(h, x_off, x_wmask, out);
}

// round 17
// speedup vs baseline: 2.1462x; 1.3923x over previous
#include <cuda_runtime.h>
#include <cuda_fp16.h>
#include <math.h>
#include <stdint.h>

// ---------------- problem constants ----------------
#define D_    768
#define H_    12
#define DH_   64
#define F_    3072
#define L_    4
#define CH_   512
#define NSEQ  16              // B * (S/CH)
#define NTOK  (NSEQ * CH_)    // 8192
#define B_    8
#define S_    1024
#define W_    512
#define LNEPS 1e-12f
#define QKVN  (3 * D_)        // 2304

// weight layout offsets within per-layer block (transposed [N,K] fp16)
#define WOFF_Q  0
#define WOFF_O  (3*D_*D_)
#define WOFF_1  (4*D_*D_)            // [N=F, K=D]
#define WOFF_2  (4*D_*D_ + D_*F_)    // [N=D, K=F]
#define WSTRIDE (4*D_*D_ + 2*D_*F_)

// ---------------- scratch (device globals; no allocs allowed) ----------------
__device__ float g_h  [NTOK * D_];
__device__ float g_h1 [NTOK * D_];
__device__ float g_tmp[NTOK * D_];
__device__ float g_qkv[NTOK * QKVN];
__device__ float g_bqkv[L_ * QKVN];

__device__ __half g_hh  [NTOK * D_];   // activations fp16
__device__ __half g_h1h [NTOK * D_];
__device__ __half g_ctxh[NTOK * D_];
__device__ __half g_midh[NTOK * F_];
__device__ __half g_wth [L_ * WSTRIDE];  // weights fp16 (single)

// ---------------- helpers ----------------
__device__ __forceinline__ float block_sum_256(float val, float* red) {
    int lane = threadIdx.x & 31, warp = threadIdx.x >> 5;
    #pragma unroll
    for (int o = 16; o > 0; o >>= 1) val += __shfl_xor_sync(0xffffffffu, val, o);
    if (lane == 0) red[warp] = val;
    __syncthreads();
    if (warp == 0) {
        float t = (lane < 8) ? red[lane] : 0.f;
        #pragma unroll
        for (int o = 4; o > 0; o >>= 1) t += __shfl_xor_sync(0xffffffffu, t, o);
        if (lane == 0) red[0] = t;
    }
    __syncthreads();
    float r = red[0];
    __syncthreads();
    return r;
}

// ---------------- batched weight transpose + fp16 convert ----------------
#define WPREP_PER_LAYER 6912
__global__ void wprep_all(const float* __restrict__ Wq, const float* __restrict__ Wk,
                          const float* __restrict__ Wv, const float* __restrict__ Wo,
                          const float* __restrict__ W1, const float* __restrict__ W2,
                          __half* __restrict__ T) {
    __shared__ float t[32][33];
    int id = blockIdx.x;
    int l = id / WPREP_PER_LAYER;
    int r = id % WPREP_PER_LAYER;

    const float* src;
    size_t doff = (size_t)l * WSTRIDE;
    int K, N, cols, local;
    if (r < 2304) {
        int mat = r / 576; local = r % 576;
        K = D_; N = D_; cols = 24;
        src = (mat == 0 ? Wq : mat == 1 ? Wk : mat == 2 ? Wv : Wo) + (size_t)l * D_ * D_;
        doff += (size_t)mat * D_ * D_;
    } else if (r < 4608) {
        local = r - 2304;
        K = D_; N = F_; cols = 96;
        src = W1 + (size_t)l * D_ * F_;
        doff += WOFF_1;
    } else {
        local = r - 4608;
        K = F_; N = D_; cols = 24;
        src = W2 + (size_t)l * F_ * D_;
        doff += WOFF_2;
    }
    int nb = (local % cols) * 32, kb = (local / cols) * 32;

    int tx = threadIdx.x, ty = threadIdx.y;
    #pragma unroll
    for (int i = 0; i < 4; i++)
        t[ty + 8 * i][tx] = src[(size_t)(kb + ty + 8 * i) * N + nb + tx];
    __syncthreads();
    #pragma unroll
    for (int i = 0; i < 4; i++) {
        float x = t[tx][ty + 8 * i];
        size_t o = doff + (size_t)(nb + ty + 8 * i) * K + kb + tx;
        T[o] = __float2half_rn(x);
    }
}

// pack [bq;bk;bv] per layer into contiguous 2304-vector
__global__ void biaspack_kernel(const float* __restrict__ bq,
                                const float* __restrict__ bk,
                                const float* __restrict__ bv,
                                float* __restrict__ dst) {
    int mat = blockIdx.x, l = blockIdx.y;
    const float* s = (mat == 0 ? bq : mat == 1 ? bk : bv) + l * D_;
    dst[(size_t)l * QKVN + mat * D_ + threadIdx.x] = s[threadIdx.x];
}

// ---------------- fused embedding + LayerNorm (+ fp16 out) ----------------
__global__ void embed_ln_kernel(const int* __restrict__ ids,
                                const float* __restrict__ we,
                                const float* __restrict__ pe,
                                const float* __restrict__ te,
                                const float* __restrict__ g,
                                const float* __restrict__ b,
                                float* __restrict__ out,
                                __half* __restrict__ oh) {
    __shared__ float red[32];
    int row = blockIdx.x;
    int pos = row % CH_;
    int id  = ids[row];
    float v[3];
    float s = 0.f;
    #pragma unroll
    for (int i = 0; i < 3; i++) {
        int d = i * 256 + threadIdx.x;
        v[i] = we[(size_t)id * D_ + d] + pe[pos * D_ + d] + te[d];
        s += v[i];
    }
    float mu = block_sum_256(s, red) * (1.f / D_);
    float sq = 0.f;
    #pragma unroll
    for (int i = 0; i < 3; i++) { float t = v[i] - mu; sq += t * t; }
    float rstd = rsqrtf(block_sum_256(sq, red) * (1.f / D_) + LNEPS);
    #pragma unroll
    for (int i = 0; i < 3; i++) {
        int d = i * 256 + threadIdx.x;
        float y = (v[i] - mu) * rstd * g[d] + b[d];
        size_t idx = (size_t)row * D_ + d;
        out[idx] = y;
        oh[idx] = __float2half_rn(y);
    }
}

// ---------------- residual + LayerNorm (+ fp16 out) ----------------
__global__ void ln_res_kernel(const float* __restrict__ X,
                              const float* __restrict__ Y,
                              const float* __restrict__ g,
                              const float* __restrict__ b,
                              float* __restrict__ out,
                              __half* __restrict__ oh) {
    __shared__ float red[32];
    int row = blockIdx.x;
    float v[3];
    float s = 0.f;
    #pragma unroll
    for (int i = 0; i < 3; i++) {
        int d = i * 256 + threadIdx.x;
        size_t idx = (size_t)row * D_ + d;
        v[i] = X[idx] + Y[idx];
        s += v[i];
    }
    float mu = block_sum_256(s, red) * (1.f / D_);
    float sq = 0.f;
    #pragma unroll
    for (int i = 0; i < 3; i++) { float t = v[i] - mu; sq += t * t; }
    float rstd = rsqrtf(block_sum_256(sq, red) * (1.f / D_) + LNEPS);
    #pragma unroll
    for (int i = 0; i < 3; i++) {
        int d = i * 256 + threadIdx.x;
        float y = (v[i] - mu) * rstd * g[d] + b[d];
        size_t idx = (size_t)row * D_ + d;
        out[idx] = y;
        oh[idx] = __float2half_rn(y);
    }
}

// ============================================================================
// fp16 tensor-core GEMM via mma.sync.m16n8k16.f32.f16.f16.f32:
// C[M,N] = A_fp16[M,K] @ B_fp16^T (B stored [N,K]) + bias (fp32 accumulate).
// CTA tile 256x128. GEMM is cp.async-ISSUE-bound (rt=8cyc/SMSP), so stage is
// minimized: A 32KB + B 16KB = 48KB, 4-stage pipeline = 192KB.
// 512 threads = 16 warps (4m x 4n), warp tile 64x32.
// ============================================================================
#define GSTAGES 4
#define STAGE_BYTES 49152u               // A 32KB | B 16KB
#define GEMM_SMEM (GSTAGES * 49152)      // 192KB

__device__ __forceinline__ void ldsm4(uint32_t* r, uint32_t addr) {
    asm volatile("ldmatrix.sync.aligned.m8n8.x4.shared.b16 {%0,%1,%2,%3}, [%4];"
                 : "=r"(r[0]), "=r"(r[1]), "=r"(r[2]), "=r"(r[3]) : "r"(addr));
}

__device__ __forceinline__ void mma16816h(float* d, const uint32_t* a, const uint32_t* b) {
    asm volatile(
        "mma.sync.aligned.m16n8k16.row.col.f32.f16.f16.f32 "
        "{%0,%1,%2,%3}, {%4,%5,%6,%7}, {%8,%9}, {%0,%1,%2,%3};"
        : "+f"(d[0]), "+f"(d[1]), "+f"(d[2]), "+f"(d[3])
        : "r"(a[0]), "r"(a[1]), "r"(a[2]), "r"(a[3]), "r"(b[0]), "r"(b[1]));
}

__device__ __forceinline__ uint32_t sw128(uint32_t off) {
    return off ^ ((off >> 3) & 0x70);
}

__device__ __forceinline__ void cp_row128(uint32_t sdst_base, const __half* src, int row) {
    #pragma unroll
    for (int i = 0; i < 8; i++) {
        uint32_t off = (uint32_t)row * 128u + (uint32_t)i * 16u;
        uint32_t d = sdst_base + sw128(off);
        asm volatile("cp.async.cg.shared.global [%0], [%1], 16;"
                     :: "r"(d), "l"(src + i * 8) : "memory");
    }
}

template <bool GELU_H>
__global__ void __launch_bounds__(512)
gemm_tc(const __half* __restrict__ A,
        const __half* __restrict__ B,
        const float* __restrict__ bias,
        float* __restrict__ Cf,
        __half* __restrict__ Ch,
        int M, int N, int K) {
    extern __shared__ char smem[];
    const int tid = threadIdx.x;
    const int wid = tid >> 5, lane = tid & 31;
    const int m0 = blockIdx.y * 256, n0 = blockIdx.x * 128;
    const int wm0 = (wid & 3) * 64;          // warp m offset (4 x 64 = 256)
    const int wn0 = (wid >> 2) * 32;         // warp n offset (4 x 32 = 128)
    const int nch = K >> 6;

    uint32_t smem_base = (uint32_t)__cvta_generic_to_shared(smem);

    // loaders: tid 0-255 -> A rows (region 0, 32KB); tid 256-383 -> B rows
    // (region 32768, 16KB); tid 384-511 idle for copies.
    const __half* srcP = nullptr;
    uint32_t tb = 0;
    int lrow = 0;
    const bool loader = tid < 384;
    if (tid < 256)      { lrow = tid;       srcP = A + (size_t)(m0 + lrow) * K; tb = 0u; }
    else if (tid < 384) { lrow = tid - 256; srcP = B + (size_t)(n0 + lrow) * K; tb = 32768u; }

    // prologue: chunks 0..2 -> stages 0..2 (one commit group per chunk)
    #pragma unroll
    for (int s = 0; s < 3; s++) {
        if (loader && s < nch) {
            uint32_t sb = smem_base + (uint32_t)s * STAGE_BYTES;
            cp_row128(sb + tb, srcP + s * 64, lrow);
        }
        asm volatile("cp.async.commit_group;" ::: "memory");
    }

    float d[4][4][4];
    #pragma unroll
    for (int mi = 0; mi < 4; mi++)
        #pragma unroll
        for (int ni = 0; ni < 4; ni++)
            #pragma unroll
            for (int j = 0; j < 4; j++) d[mi][ni][j] = 0.f;

    const int mat = lane >> 3;
    const int rin = lane & 7;
    const int rowadd = (mat & 1) * 8 + rin;
    const int bytadd = (mat >> 1) * 16;

    for (int c = 0; c < nch; c++) {
        asm volatile("cp.async.wait_group 2;" ::: "memory");  // chunk c complete
        __syncthreads();   // all warps done with stage (c-1)%4; chunk c visible

        // issue chunk c+3 into stage (c+3)%4 (freed by compute of chunk c-1)
        if (loader && c + 3 < nch) {
            uint32_t sb = smem_base + (uint32_t)((c + 3) & 3) * STAGE_BYTES;
            cp_row128(sb + tb, srcP + ((c + 3) << 6), lrow);
        }
        asm volatile("cp.async.commit_group;" ::: "memory");  // always (may be empty)

        uint32_t sb = smem_base + (uint32_t)(c & 3) * STAGE_BYTES;
        #pragma unroll
        for (int ks = 0; ks < 4; ks++) {
            const int kbyte = ks * 32 + bytadd;
            uint32_t ah[4][4];
            #pragma unroll
            for (int mi = 0; mi < 4; mi++) {
                uint32_t off = sw128((uint32_t)(wm0 + mi * 16 + rowadd) * 128u + kbyte);
                ldsm4(ah[mi], sb + off);
            }
            uint32_t bfr[4][2];
            #pragma unroll
            for (int np = 0; np < 2; np++) {
                uint32_t off = sw128((uint32_t)(wn0 + np * 16 + rowadd) * 128u + kbyte);
                uint32_t t4[4];
                ldsm4(t4, sb + 32768u + off);
                bfr[np * 2][0]     = t4[0]; bfr[np * 2][1]     = t4[2];
                bfr[np * 2 + 1][0] = t4[1]; bfr[np * 2 + 1][1] = t4[3];
            }
            #pragma unroll
            for (int mi = 0; mi < 4; mi++)
                #pragma unroll
                for (int ni = 0; ni < 4; ni++)
                    mma16816h(d[mi][ni], ah[mi], bfr[ni]);
        }
    }

    // ---------------- epilogue ----------------
    const int qr = lane >> 2;
    const int qc = (lane & 3) * 2;
    #pragma unroll
    for (int mi = 0; mi < 4; mi++) {
        #pragma unroll
        for (int half = 0; half < 2; half++) {
            int m = m0 + wm0 + mi * 16 + half * 8 + qr;
            #pragma unroll
            for (int ni = 0; ni < 4; ni++) {
                int n = n0 + wn0 + ni * 8 + qc;
                float x0 = d[mi][ni][half * 2 + 0] + __ldg(bias + n + 0);
                float x1 = d[mi][ni][half * 2 + 1] + __ldg(bias + n + 1);
                if (!GELU_H) {
                    float2 o; o.x = x0; o.y = x1;
                    *(float2*)(Cf + (size_t)m * N + n) = o;
                } else {
                    x0 = 0.5f * x0 * (1.f + erff(x0 * 0.70710678118654752f));
                    x1 = 0.5f * x1 * (1.f + erff(x1 * 0.70710678118654752f));
                    __half2 p;
                    p.x = __float2half_rn(x0);
                    p.y = __float2half_rn(x1);
                    *(__half2*)(Ch + (size_t)m * N + n) = p;
                }
            }
        }
    }
}

// ---------------- fused attention (flash-style, fp32; fp16 ctx out) ----------------
// Reads packed QKV [NTOK, 2304]: Q at +0, K at +768, V at +1536.
#define ATTN_SMEM (4 * 64 * 65 * 4)
__global__ void attn_kernel(const float* __restrict__ QKV,
                            const float* __restrict__ bmask,
                            __half* __restrict__ CtxH) {
    extern __shared__ float sm[];
    float* Qs = sm;                  // [64][65]
    float* Ks = Qs + 64 * 65;
    float* Vs = Ks + 64 * 65;
    float* Ps = Vs + 64 * 65;

    int qt = blockIdx.x, bh = blockIdx.y;
    int bp = bh / H_, hd = bh % H_;
    int tx = threadIdx.x & 15, ty = threadIdx.x >> 4;
    const float scale = 0.125f;

    {
        int r = threadIdx.x >> 2;
        int cseg = (threadIdx.x & 3) * 16;
        int grow = bp * CH_ + qt * 64 + r;
        const float* gp = QKV + (size_t)grow * QKVN + hd * DH_ + cseg;
        #pragma unroll
        for (int u = 0; u < 4; u++) {
            float4 t = *(const float4*)(gp + 4 * u);
            Qs[r * 65 + cseg + 4 * u + 0] = t.x;
            Qs[r * 65 + cseg + 4 * u + 1] = t.y;
            Qs[r * 65 + cseg + 4 * u + 2] = t.z;
            Qs[r * 65 + cseg + 4 * u + 3] = t.w;
        }
    }

    float mi[4], li[4], o[4][4];
    #pragma unroll
    for (int i = 0; i < 4; i++) {
        mi[i] = -1e30f; li[i] = 0.f;
        #pragma unroll
        for (int j = 0; j < 4; j++) o[i][j] = 0.f;
    }

    for (int kt = 0; kt < CH_ / 64; kt++) {
        __syncthreads();
        {
            int r = threadIdx.x >> 2;
            int cseg = (threadIdx.x & 3) * 16;
            int grow = bp * CH_ + kt * 64 + r;
            const float* gk = QKV + (size_t)grow * QKVN + D_ + hd * DH_ + cseg;
            const float* gv = QKV + (size_t)grow * QKVN + 2 * D_ + hd * DH_ + cseg;
            #pragma unroll
            for (int u = 0; u < 4; u++) {
                float4 t = *(const float4*)(gk + 4 * u);
                Ks[r * 65 + cseg + 4 * u + 0] = t.x;
                Ks[r * 65 + cseg + 4 * u + 1] = t.y;
                Ks[r * 65 + cseg + 4 * u + 2] = t.z;
                Ks[r * 65 + cseg + 4 * u + 3] = t.w;
                float4 s = *(const float4*)(gv + 4 * u);
                Vs[r * 65 + cseg + 4 * u + 0] = s.x;
                Vs[r * 65 + cseg + 4 * u + 1] = s.y;
                Vs[r * 65 + cseg + 4 * u + 2] = s.z;
                Vs[r * 65 + cseg + 4 * u + 3] = s.w;
            }
        }
        __syncthreads();

        float biasj[4];
        #pragma unroll
        for (int j = 0; j < 4; j++) {
            float mv = bmask[bp * CH_ + kt * 64 + tx * 4 + j];
            biasj[j] = (1.f - mv) * -10000.f;
        }

        float s[4][4] = {};
        #pragma unroll 8
        for (int dd = 0; dd < 64; dd++) {
            float av[4], bv[4];
            #pragma unroll
            for (int i = 0; i < 4; i++) av[i] = Qs[(ty * 4 + i) * 65 + dd];
            #pragma unroll
            for (int j = 0; j < 4; j++) bv[j] = Ks[(tx * 4 + j) * 65 + dd];
            #pragma unroll
            for (int i = 0; i < 4; i++)
                #pragma unroll
                for (int j = 0; j < 4; j++)
                    s[i][j] = fmaf(av[i], bv[j], s[i][j]);
        }
        #pragma unroll
        for (int i = 0; i < 4; i++)
            #pragma unroll
            for (int j = 0; j < 4; j++)
                s[i][j] = s[i][j] * scale + biasj[j];

        float p[4][4];
        #pragma unroll
        for (int i = 0; i < 4; i++) {
            float rm = fmaxf(fmaxf(s[i][0], s[i][1]), fmaxf(s[i][2], s[i][3]));
            #pragma unroll
            for (int off = 1; off <= 8; off <<= 1)
                rm = fmaxf(rm, __shfl_xor_sync(0xffffffffu, rm, off));
            float mnew = fmaxf(mi[i], rm);
            float c = __expf(mi[i] - mnew);
            float rs = 0.f;
            #pragma unroll
            for (int j = 0; j < 4; j++) { p[i][j] = __expf(s[i][j] - mnew); rs += p[i][j]; }
            #pragma unroll
            for (int off = 1; off <= 8; off <<= 1)
                rs += __shfl_xor_sync(0xffffffffu, rs, off);
            li[i] = li[i] * c + rs;
            mi[i] = mnew;
            #pragma unroll
            for (int j = 0; j < 4; j++) o[i][j] *= c;
        }

        #pragma unroll
        for (int i = 0; i < 4; i++)
            #pragma unroll
            for (int j = 0; j < 4; j++)
                Ps[(ty * 4 + i) * 65 + tx * 4 + j] = p[i][j];
        __syncthreads();

        #pragma unroll 8
        for (int kk = 0; kk < 64; kk++) {
            float av[4], bv[4];
            #pragma unroll
            for (int i = 0; i < 4; i++) av[i] = Ps[(ty * 4 + i) * 65 + kk];
            #pragma unroll
            for (int j = 0; j < 4; j++) bv[j] = Vs[kk * 65 + tx * 4 + j];
            #pragma unroll
            for (int i = 0; i < 4; i++)
                #pragma unroll
                for (int j = 0; j < 4; j++)
                    o[i][j] = fmaf(av[i], bv[j], o[i][j]);
        }
    }

    #pragma unroll
    for (int i = 0; i < 4; i++) {
        float inv = 1.f / li[i];
        int grow = bp * CH_ + qt * 64 + ty * 4 + i;
        size_t base = (size_t)grow * D_ + hd * DH_ + tx * 4;
        #pragma unroll
        for (int j = 0; j < 4; j++)
            CtxH[base + j] = __float2half_rn(o[i][j] * inv);
    }
}

// ---------------- offset mean pooling ----------------
__global__ void pool_kernel(const float* __restrict__ emb,
                            const int* __restrict__ offset,
                            const int* __restrict__ xmask,
                            float* __restrict__ out) {
    int w = blockIdx.x, b = blockIdx.y;
    int st = offset[((size_t)b * W_ + w) * 2 + 0];
    int ed = offset[((size_t)b * W_ + w) * 2 + 1];
    bool valid = (xmask[b * W_ + w] != 0) && (st < ed);
    float acc[3] = {0.f, 0.f, 0.f};
    if (valid) {
        for (int s = st; s < ed; s++) {
            const float* rp = emb + ((size_t)b * S_ + s) * D_;
            #pragma unroll
            for (int i = 0; i < 3; i++) acc[i] += rp[i * 256 + threadIdx.x];
        }
    }
    float inv = valid ? 1.f / fmaxf((float)(ed - st), 1.f) : 0.f;
    float* op = out + ((size_t)b * W_ + w) * D_;
    #pragma unroll
    for (int i = 0; i < 3; i++) op[i * 256 + threadIdx.x] = acc[i] * inv;
}

// ---------------- launcher ----------------
extern "C" void kernel_launch(void* const* d_in, const int* in_sizes, int n_in,
                              void* d_out, int out_size) {
    const int*   x_bert   = (const int*)  d_in[0];
    const float* x_mask_f = (const float*)d_in[1];
    const int*   x_off    = (const int*)  d_in[2];
    const int*   x_wmask  = (const int*)  d_in[3];
    const float* word_emb = (const float*)d_in[4];
    const float* pos_emb  = (const float*)d_in[5];
    const float* type_emb = (const float*)d_in[6];
    const float* emb_g    = (const float*)d_in[7];
    const float* emb_b    = (const float*)d_in[8];
    const float* Wq = (const float*)d_in[9];   const float* bq = (const float*)d_in[10];
    const float* Wk = (const float*)d_in[11];  const float* bk = (const float*)d_in[12];
    const float* Wv = (const float*)d_in[13];  const float* bv = (const float*)d_in[14];
    const float* Wo = (const float*)d_in[15];  const float* bo = (const float*)d_in[16];
    const float* ln1_g = (const float*)d_in[17]; const float* ln1_b = (const float*)d_in[18];
    const float* W1 = (const float*)d_in[19];  const float* b1f = (const float*)d_in[20];
    const float* W2 = (const float*)d_in[21];  const float* b2f = (const float*)d_in[22];
    const float* ln2_g = (const float*)d_in[23]; const float* ln2_b = (const float*)d_in[24];
    float* out = (float*)d_out;

    float *h, *h1, *tmp, *qkv, *bqkv;
    __half *hh, *h1h, *ctxh, *midh, *wth;
    cudaGetSymbolAddress((void**)&h,    g_h);
    cudaGetSymbolAddress((void**)&h1,   g_h1);
    cudaGetSymbolAddress((void**)&tmp,  g_tmp);
    cudaGetSymbolAddress((void**)&qkv,  g_qkv);
    cudaGetSymbolAddress((void**)&bqkv, g_bqkv);
    cudaGetSymbolAddress((void**)&hh,   g_hh);
    cudaGetSymbolAddress((void**)&h1h,  g_h1h);
    cudaGetSymbolAddress((void**)&ctxh, g_ctxh);
    cudaGetSymbolAddress((void**)&midh, g_midh);
    cudaGetSymbolAddress((void**)&wth,  g_wth);

    cudaFuncSetAttribute(attn_kernel, cudaFuncAttributeMaxDynamicSharedMemorySize, ATTN_SMEM);
    cudaFuncSetAttribute(gemm_tc<false>, cudaFuncAttributeMaxDynamicSharedMemorySize, GEMM_SMEM);
    cudaFuncSetAttribute(gemm_tc<true>,  cudaFuncAttributeMaxDynamicSharedMemorySize, GEMM_SMEM);

    // (0) weight prep: ONE launch for all layers/matrices; (1) bias pack
    wprep_all<<<L_ * WPREP_PER_LAYER, dim3(32, 8)>>>(Wq, Wk, Wv, Wo, W1, W2, wth);
    biaspack_kernel<<<dim3(3, L_), D_>>>(bq, bk, bv, bqkv);

    // (2) embedding + LN
    embed_ln_kernel<<<NTOK, 256>>>(x_bert, word_emb, pos_emb, type_emb, emb_g, emb_b, h, hh);

    dim3 gQKV(QKVN / 128, NTOK / 256);  // (18, 32)
    dim3 gD(D_ / 128, NTOK / 256);      // (6, 32)
    dim3 gF(F_ / 128, NTOK / 256);      // (24, 32)

    for (int l = 0; l < L_; l++) {
        size_t wb = (size_t)l * WSTRIDE;

        // fused QKV GEMM: N = 2304
        gemm_tc<false><<<gQKV, 512, GEMM_SMEM>>>(hh, wth + wb,
                                                 bqkv + (size_t)l * QKVN, qkv,
                                                 nullptr, NTOK, QKVN, D_);

        attn_kernel<<<dim3(CH_ / 64, NSEQ * H_), 256, ATTN_SMEM>>>(qkv, x_mask_f, ctxh);

        gemm_tc<false><<<gD, 512, GEMM_SMEM>>>(ctxh, wth + wb + WOFF_O,
                                               bo + l * D_, tmp, nullptr, NTOK, D_, D_);
        ln_res_kernel<<<NTOK, 256>>>(h, tmp, ln1_g + l * D_, ln1_b + l * D_, h1, h1h);

        gemm_tc<true><<<gF, 512, GEMM_SMEM>>>(h1h, wth + wb + WOFF_1,
                                              b1f + l * F_, nullptr, midh, NTOK, F_, D_);
        gemm_tc<false><<<gD, 512, GEMM_SMEM>>>(midh, wth + wb + WOFF_2,
                                               b2f + l * D_, tmp, nullptr, NTOK, D_, F_);
        ln_res_kernel<<<NTOK, 256>>>(h1, tmp, ln2_g + l * D_, ln2_b + l * D_, h, hh);
    }

    pool_kernel<<<dim3(W_, B_), 256>>>(h, x_off, x_wmask, out);
}